// round 5
// baseline (speedup 1.0000x reference)
#include <cuda_runtime.h>
#include <math.h>

#define BB 4
#define TT 16
#define HH 64
#define WW 64
#define CIN 32
#define COUT 64
#define GG (4*COUT)   // 256 gate channels

typedef unsigned long long u64;

// Scratch: gx for all (b,t) pixels: (B*T*H*W, 256) floats = 268MB
__device__ float g_gx[(size_t)BB*TT*HH*WW*GG];
// Duplicated ping-pong hidden state: each channel stored as {h,h} pair (8MB each)
__device__ float g_h0d[(size_t)BB*HH*WW*COUT*2];
__device__ float g_h1d[(size_t)BB*HH*WW*COUT*2];
// Cell state
__device__ float g_c [(size_t)BB*HH*WW*COUT];
// Transposed-interleaved weights: [k][ci][lane(32)][8 = 4 gates x 2 ch]
__device__ float g_rwT[9*COUT*32*8];   // 589KB
__device__ float g_wkT[9*CIN*32*8];    // 295KB

__device__ __forceinline__ float hsig(float z) {
    return fminf(fmaxf(0.2f*z + 0.5f, 0.0f), 1.0f);
}

// Packed dual-FMA: acc.{lo,hi} += s.{lo,hi} * w.{lo,hi}
__device__ __forceinline__ void fma_x2(u64& acc, u64 s, u64 w) {
    asm("fma.rn.f32x2 %0, %1, %2, %3;" : "=l"(acc) : "l"(s), "l"(w), "l"(acc));
}
__device__ __forceinline__ u64 pack2(float s) {
    u64 r;
    asm("mov.b64 %0, {%1, %1};" : "=l"(r) : "f"(s));
    return r;
}
__device__ __forceinline__ float2 unpack2(u64 v) {
    float2 f;
    asm("mov.b64 {%0, %1}, %2;" : "=f"(f.x), "=f"(f.y) : "l"(v));
    return f;
}

// ---------------------------------------------------------------------------
// Weight transpose prep: for each (k, ci, lane j) gather the 8 floats
// {g0c0,g0c1, g1c0,g1c1, g2c0,g2c1, g3c0,g3c1} with c0=2j, c1=2j+1.
// ---------------------------------------------------------------------------
__global__ __launch_bounds__(128)
void prep_weights(const float* __restrict__ wk, const float* __restrict__ rw)
{
    const int i = blockIdx.x * 128 + threadIdx.x;
    if (i < 9*COUT*32) {
        const int j  = i & 31;
        const int ci = (i >> 5) & 63;
        const int k  = i >> 11;
        const float* s = rw + ((size_t)(k*COUT + ci))*GG + 2*j;
        float4 a = make_float4(s[0],   s[1],   s[64],  s[65]);
        float4 b = make_float4(s[128], s[129], s[192], s[193]);
        float4* d = (float4*)(g_rwT + (size_t)i*8);
        d[0] = a; d[1] = b;
    }
    const int m = i - 9*COUT*32;
    if (m >= 0 && m < 9*CIN*32) {
        const int j  = m & 31;
        const int ci = (m >> 5) & 31;
        const int k  = m >> 10;
        const float* s = wk + ((size_t)(k*CIN + ci))*GG + 2*j;
        float4 a = make_float4(s[0],   s[1],   s[64],  s[65]);
        float4 b = make_float4(s[128], s[129], s[192], s[193]);
        float4* d = (float4*)(g_wkT + (size_t)m*8);
        d[0] = a; d[1] = b;
    }
}

// ---------------------------------------------------------------------------
// Phase 1: input-to-gate conv.
// Thread: 4 pixels x (2 channels x 4 gates) = 16 packed accumulators.
// Block: 128 thr = 4 warps (pixel groups) x 32 lanes (channel pairs).
// Grid: B*T*H*4 = 16384.
// ---------------------------------------------------------------------------
__global__ __launch_bounds__(128, 5)
void input_conv_kernel(const float* __restrict__ x,
                       const float* __restrict__ bias)
{
    const int tx   = threadIdx.x;
    const int lane = tx & 31;
    const int co0  = lane * 2;
    const int pg   = tx >> 5;
    const int bid  = blockIdx.x;
    const int bt   = bid >> 8;
    const int r    = bid & 255;
    const int py   = r >> 2;
    const int px0  = (r & 3) * 16 + pg * 4;
    const bool okL = (px0 > 0);
    const bool okR = (px0 < WW - 4);

    u64 acc[4][4];
    #pragma unroll
    for (int g = 0; g < 4; g++) {
        u64 bv = *(const u64*)(bias + g*COUT + co0);
        #pragma unroll
        for (int p = 0; p < 4; p++) acc[g][p] = bv;
    }

    #pragma unroll
    for (int ky = 0; ky < 3; ky++) {
        const int iy = py + ky - 1;
        if ((unsigned)iy >= HH) continue;
        const float* __restrict__ xrow = x + ((size_t)(bt*HH + iy)*WW)*CIN;
        #pragma unroll 2
        for (int ci = 0; ci < CIN; ci++) {
            u64 hv2[6];
            hv2[0] = okL ? pack2(xrow[(size_t)(px0-1)*CIN + ci]) : 0ULL;
            #pragma unroll
            for (int j = 1; j < 5; j++)
                hv2[j] = pack2(xrow[(size_t)(px0-1+j)*CIN + ci]);
            hv2[5] = okR ? pack2(xrow[(size_t)(px0+4)*CIN + ci]) : 0ULL;
            #pragma unroll
            for (int kx = 0; kx < 3; kx++) {
                const ulonglong2* __restrict__ wp = (const ulonglong2*)
                    (g_wkT + (((size_t)(ky*3+kx)*CIN + ci)*32 + lane)*8);
                ulonglong2 wA = wp[0];   // gates 0,1
                ulonglong2 wB = wp[1];   // gates 2,3
                #pragma unroll
                for (int p = 0; p < 4; p++) {
                    const u64 s2 = hv2[p + kx];
                    fma_x2(acc[0][p], s2, wA.x);
                    fma_x2(acc[1][p], s2, wA.y);
                    fma_x2(acc[2][p], s2, wB.x);
                    fma_x2(acc[3][p], s2, wB.y);
                }
            }
        }
    }

    const size_t rowbase = ((size_t)bt*HH + py)*WW;
    #pragma unroll
    for (int p = 0; p < 4; p++) {
        float* __restrict__ o = g_gx + (rowbase + px0 + p)*GG + co0;
        *(u64*)(o + 0*COUT) = acc[0][p];
        *(u64*)(o + 1*COUT) = acc[1][p];
        *(u64*)(o + 2*COUT) = acc[2][p];
        *(u64*)(o + 3*COUT) = acc[3][p];
    }
}

// ---------------------------------------------------------------------------
// Phase 2: one recurrent step. h stored duplicated ({h,h} per channel) so
// halo reads are direct LDG.64 of the packed broadcast operand.
// Block: 128 thr = 4 warps x 32 lanes. Grid: B*H*4 = 1024.
// ---------------------------------------------------------------------------
template<bool FIRST>
__global__ __launch_bounds__(128, 5)
void step_kernel(float* __restrict__ y,
                 const int t,
                 const float* __restrict__ gamma,
                 const float* __restrict__ beta,
                 const float* __restrict__ mmean,
                 const float* __restrict__ mvar)
{
    const float* __restrict__ hprevd = (t & 1) ? g_h0d : g_h1d;
    float*       __restrict__ hnewd  = (t & 1) ? g_h1d : g_h0d;

    const int tx   = threadIdx.x;
    const int lane = tx & 31;
    const int co0  = lane * 2;
    const int pg   = tx >> 5;
    const int bid  = blockIdx.x;
    const int b    = bid >> 8;
    const int r    = bid & 255;
    const int py   = r >> 2;
    const int px0  = (r & 3) * 16 + pg * 4;
    const bool okL = (px0 > 0);
    const bool okR = (px0 < WW - 4);

    u64 acc[4][4];
    const size_t gxrow = ((size_t)(b*TT + t)*HH + py)*WW;
    #pragma unroll
    for (int p = 0; p < 4; p++) {
        const float* __restrict__ gp = g_gx + (gxrow + px0 + p)*GG + co0;
        acc[0][p] = *(const u64*)(gp + 0*COUT);
        acc[1][p] = *(const u64*)(gp + 1*COUT);
        acc[2][p] = *(const u64*)(gp + 2*COUT);
        acc[3][p] = *(const u64*)(gp + 3*COUT);
    }

    if (!FIRST) {
        #pragma unroll
        for (int ky = 0; ky < 3; ky++) {
            const int iy = py + ky - 1;
            if ((unsigned)iy >= HH) continue;
            // 128 floats per pixel (64 channels duplicated)
            const float* __restrict__ hrow = hprevd + ((size_t)(b*HH + iy)*WW)*(COUT*2);
            #pragma unroll 2
            for (int ci = 0; ci < COUT; ci++) {
                u64 hv2[6];
                hv2[0] = okL ? *(const u64*)(hrow + (size_t)(px0-1)*(COUT*2) + ci*2) : 0ULL;
                #pragma unroll
                for (int j = 1; j < 5; j++)
                    hv2[j] = *(const u64*)(hrow + (size_t)(px0-1+j)*(COUT*2) + ci*2);
                hv2[5] = okR ? *(const u64*)(hrow + (size_t)(px0+4)*(COUT*2) + ci*2) : 0ULL;
                #pragma unroll
                for (int kx = 0; kx < 3; kx++) {
                    const ulonglong2* __restrict__ wp = (const ulonglong2*)
                        (g_rwT + (((size_t)(ky*3+kx)*COUT + ci)*32 + lane)*8);
                    ulonglong2 wA = wp[0];   // gates 0,1
                    ulonglong2 wB = wp[1];   // gates 2,3
                    #pragma unroll
                    for (int p = 0; p < 4; p++) {
                        const u64 s2 = hv2[p + kx];
                        fma_x2(acc[0][p], s2, wA.x);
                        fma_x2(acc[1][p], s2, wA.y);
                        fma_x2(acc[2][p], s2, wB.x);
                        fma_x2(acc[3][p], s2, wB.y);
                    }
                }
            }
        }
    }

    // BN constants for this thread's 2 channels
    float2 gm  = *(const float2*)(gamma + co0);
    float2 bt2 = *(const float2*)(beta  + co0);
    float2 mm  = *(const float2*)(mmean + co0);
    float2 mv  = *(const float2*)(mvar  + co0);
    float2 inv, add;
    inv.x = gm.x * rsqrtf(mv.x + 1e-3f); add.x = bt2.x - mm.x*inv.x;
    inv.y = gm.y * rsqrtf(mv.y + 1e-3f); add.y = bt2.y - mm.y*inv.y;

    const size_t pixrow = ((size_t)b*HH + py)*WW;
    #pragma unroll
    for (int p = 0; p < 4; p++) {
        const size_t pix = pixrow + px0 + p;

        float2 gi = unpack2(acc[0][p]);
        float2 gf = unpack2(acc[1][p]);
        float2 gg = unpack2(acc[2][p]);
        float2 go = unpack2(acc[3][p]);

        float2 i2, f2, o2;
        i2.x = hsig(gi.x); i2.y = hsig(gi.y);
        f2.x = hsig(gf.x); f2.y = hsig(gf.y);
        o2.x = hsig(go.x); o2.y = hsig(go.y);

        float* __restrict__ cp = g_c + pix*COUT + co0;
        float2 cold = FIRST ? make_float2(0.f,0.f) : *(const float2*)cp;

        float2 cn;
        cn.x = f2.x*cold.x + i2.x*tanhf(gg.x);
        cn.y = f2.y*cold.y + i2.y*tanhf(gg.y);
        *(float2*)cp = cn;

        float2 h2;
        h2.x = o2.x * tanhf(cn.x);
        h2.y = o2.y * tanhf(cn.y);
        // duplicated store {h.x,h.x,h.y,h.y}
        *(float4*)(hnewd + pix*(COUT*2) + co0*2) = make_float4(h2.x, h2.x, h2.y, h2.y);

        float2 yv;
        yv.x = h2.x*inv.x + add.x;
        yv.y = h2.y*inv.y + add.y;
        float* __restrict__ yp = y + (gxrow + px0 + p)*COUT + co0;
        *(float2*)yp = yv;
    }
}

extern "C" void kernel_launch(void* const* d_in, const int* in_sizes, int n_in,
                              void* d_out, int out_size)
{
    const float* x      = (const float*)d_in[0];
    const float* wk     = (const float*)d_in[1];
    const float* rw     = (const float*)d_in[2];
    const float* bias   = (const float*)d_in[3];
    const float* gamma  = (const float*)d_in[4];
    const float* beta   = (const float*)d_in[5];
    const float* mmean  = (const float*)d_in[6];
    const float* mvar   = (const float*)d_in[7];
    float* y = (float*)d_out;

    // Prep: transpose/interleave weights (one-time per launch, trivial cost).
    const int n_prep = 9*COUT*32 + 9*CIN*32;
    prep_weights<<<(n_prep + 127)/128, 128>>>(wk, rw);

    // Phase 1: all input convs. 16384 blocks x 128 threads (16 px each).
    input_conv_kernel<<<BB*TT*HH*4, 128>>>(x, bias);

    // Phase 2: 16 sequential recurrent steps. 1024 blocks x 128 threads.
    const int nblk = BB*HH*4;
    step_kernel<true><<<nblk, 128>>>(y, 0, gamma, beta, mmean, mvar);
    for (int t = 1; t < TT; t++) {
        step_kernel<false><<<nblk, 128>>>(y, t, gamma, beta, mmean, mvar);
    }
}

// round 6
// speedup vs baseline: 1.3196x; 1.3196x over previous
#include <cuda_runtime.h>
#include <math.h>

#define BB 4
#define TT 16
#define HH 64
#define WW 64
#define CIN 32
#define COUT 64
#define GG (4*COUT)   // 256 gate channels

typedef unsigned long long u64;

// Scratch: gx for all (b,t) pixels: (B*T*H*W, 256) floats = 268MB
__device__ float g_gx[(size_t)BB*TT*HH*WW*GG];
// Duplicated ping-pong hidden state: each channel stored as {h,h} pair
__device__ float g_h0d[(size_t)BB*HH*WW*COUT*2];
__device__ float g_h1d[(size_t)BB*HH*WW*COUT*2];
// Cell state
__device__ float g_c [(size_t)BB*HH*WW*COUT];
// Split transposed weights: [k][ci][lane(32)][4 floats]
// g01: {g0c0,g0c1,g1c0,g1c1}   g23: {g2c0,g2c1,g3c0,g3c1}   (c0=2*lane)
__device__ float g_rw01[9*COUT*32*4];
__device__ float g_rw23[9*COUT*32*4];
__device__ float g_wk01[9*CIN*32*4];
__device__ float g_wk23[9*CIN*32*4];

__device__ __forceinline__ float hsig(float z) {
    return fminf(fmaxf(0.2f*z + 0.5f, 0.0f), 1.0f);
}

__device__ __forceinline__ void fma_x2(u64& acc, u64 s, u64 w) {
    asm("fma.rn.f32x2 %0, %1, %2, %3;" : "=l"(acc) : "l"(s), "l"(w), "l"(acc));
}
__device__ __forceinline__ u64 pack2(float s) {
    u64 r;
    asm("mov.b64 %0, {%1, %1};" : "=l"(r) : "f"(s));
    return r;
}
__device__ __forceinline__ float2 unpack2(u64 v) {
    float2 f;
    asm("mov.b64 {%0, %1}, %2;" : "=f"(f.x), "=f"(f.y) : "l"(v));
    return f;
}

// ---------------------------------------------------------------------------
// Weight transpose prep.
// ---------------------------------------------------------------------------
__global__ __launch_bounds__(128)
void prep_weights(const float* __restrict__ wk, const float* __restrict__ rw)
{
    const int i = blockIdx.x * 128 + threadIdx.x;
    if (i < 9*COUT*32) {
        const int j  = i & 31;
        const int ci = (i >> 5) & 63;
        const int k  = i >> 11;
        const float* s = rw + ((size_t)(k*COUT + ci))*GG + 2*j;
        ((float4*)g_rw01)[i] = make_float4(s[0],   s[1],   s[64],  s[65]);
        ((float4*)g_rw23)[i] = make_float4(s[128], s[129], s[192], s[193]);
    }
    const int m = i - 9*COUT*32;
    if (m >= 0 && m < 9*CIN*32) {
        const int j  = m & 31;
        const int ci = (m >> 5) & 31;
        const int k  = m >> 10;
        const float* s = wk + ((size_t)(k*CIN + ci))*GG + 2*j;
        ((float4*)g_wk01)[m] = make_float4(s[0],   s[1],   s[64],  s[65]);
        ((float4*)g_wk23)[m] = make_float4(s[128], s[129], s[192], s[193]);
    }
}

// ---------------------------------------------------------------------------
// Phase 1: input-to-gate conv.
// Thread: 4 pixels x (2 channels x 4 gates) = 16 packed accumulators.
// Block: 128 thr = 4 warps (pixel groups) x 32 lanes (channel pairs).
// Grid: B*T*H*4 = 16384.
// ---------------------------------------------------------------------------
__global__ __launch_bounds__(128, 5)
void input_conv_kernel(const float* __restrict__ x,
                       const float* __restrict__ bias)
{
    const int tx   = threadIdx.x;
    const int lane = tx & 31;
    const int co0  = lane * 2;
    const int pg   = tx >> 5;
    const int bid  = blockIdx.x;
    const int bt   = bid >> 8;
    const int r    = bid & 255;
    const int py   = r >> 2;
    const int px0  = (r & 3) * 16 + pg * 4;
    const bool okL = (px0 > 0);
    const bool okR = (px0 < WW - 4);

    u64 acc[4][4];
    #pragma unroll
    for (int g = 0; g < 4; g++) {
        u64 bv = *(const u64*)(bias + g*COUT + co0);
        #pragma unroll
        for (int p = 0; p < 4; p++) acc[g][p] = bv;
    }

    #pragma unroll
    for (int ky = 0; ky < 3; ky++) {
        const int iy = py + ky - 1;
        if ((unsigned)iy >= HH) continue;
        const float* __restrict__ xrow = x + ((size_t)(bt*HH + iy)*WW)*CIN;
        #pragma unroll 1
        for (int ci = 0; ci < CIN; ci++) {
            u64 hv2[6];
            hv2[0] = okL ? pack2(xrow[(size_t)(px0-1)*CIN + ci]) : 0ULL;
            #pragma unroll
            for (int j = 1; j < 5; j++)
                hv2[j] = pack2(xrow[(size_t)(px0-1+j)*CIN + ci]);
            hv2[5] = okR ? pack2(xrow[(size_t)(px0+4)*CIN + ci]) : 0ULL;
            #pragma unroll
            for (int kx = 0; kx < 3; kx++) {
                const size_t widx = ((size_t)(ky*3+kx)*CIN + ci)*32 + lane;
                ulonglong2 wA = ((const ulonglong2*)g_wk01)[widx];  // g0,g1
                ulonglong2 wB = ((const ulonglong2*)g_wk23)[widx];  // g2,g3
                #pragma unroll
                for (int p = 0; p < 4; p++) {
                    const u64 s2 = hv2[p + kx];
                    fma_x2(acc[0][p], s2, wA.x);
                    fma_x2(acc[1][p], s2, wA.y);
                    fma_x2(acc[2][p], s2, wB.x);
                    fma_x2(acc[3][p], s2, wB.y);
                }
            }
        }
    }

    const size_t rowbase = ((size_t)bt*HH + py)*WW;
    #pragma unroll
    for (int p = 0; p < 4; p++) {
        float* __restrict__ o = g_gx + (rowbase + px0 + p)*GG + co0;
        *(u64*)(o + 0*COUT) = acc[0][p];
        *(u64*)(o + 1*COUT) = acc[1][p];
        *(u64*)(o + 2*COUT) = acc[2][p];
        *(u64*)(o + 3*COUT) = acc[3][p];
    }
}

// ---------------------------------------------------------------------------
// Phase 2: one recurrent step. h stored duplicated ({h,h} per channel) so
// halo reads are direct LDG.64 of the packed broadcast operand.
// Block: 128 thr = 4 warps x 32 lanes. Grid: B*H*4 = 1024.
// ---------------------------------------------------------------------------
template<bool FIRST>
__global__ __launch_bounds__(128, 5)
void step_kernel(float* __restrict__ y,
                 const int t,
                 const float* __restrict__ gamma,
                 const float* __restrict__ beta,
                 const float* __restrict__ mmean,
                 const float* __restrict__ mvar)
{
    const float* __restrict__ hprevd = (t & 1) ? g_h0d : g_h1d;
    float*       __restrict__ hnewd  = (t & 1) ? g_h1d : g_h0d;

    const int tx   = threadIdx.x;
    const int lane = tx & 31;
    const int co0  = lane * 2;
    const int pg   = tx >> 5;
    const int bid  = blockIdx.x;
    const int b    = bid >> 8;
    const int r    = bid & 255;
    const int py   = r >> 2;
    const int px0  = (r & 3) * 16 + pg * 4;
    const bool okL = (px0 > 0);
    const bool okR = (px0 < WW - 4);

    u64 acc[4][4];
    const size_t gxrow = ((size_t)(b*TT + t)*HH + py)*WW;
    #pragma unroll
    for (int p = 0; p < 4; p++) {
        const float* __restrict__ gp = g_gx + (gxrow + px0 + p)*GG + co0;
        acc[0][p] = *(const u64*)(gp + 0*COUT);
        acc[1][p] = *(const u64*)(gp + 1*COUT);
        acc[2][p] = *(const u64*)(gp + 2*COUT);
        acc[3][p] = *(const u64*)(gp + 3*COUT);
    }

    if (!FIRST) {
        #pragma unroll
        for (int ky = 0; ky < 3; ky++) {
            const int iy = py + ky - 1;
            if ((unsigned)iy >= HH) continue;
            const float* __restrict__ hrow = hprevd + ((size_t)(b*HH + iy)*WW)*(COUT*2);
            #pragma unroll 1
            for (int ci = 0; ci < COUT; ci++) {
                u64 hv2[6];
                hv2[0] = okL ? *(const u64*)(hrow + (size_t)(px0-1)*(COUT*2) + ci*2) : 0ULL;
                #pragma unroll
                for (int j = 1; j < 5; j++)
                    hv2[j] = *(const u64*)(hrow + (size_t)(px0-1+j)*(COUT*2) + ci*2);
                hv2[5] = okR ? *(const u64*)(hrow + (size_t)(px0+4)*(COUT*2) + ci*2) : 0ULL;
                #pragma unroll
                for (int kx = 0; kx < 3; kx++) {
                    const size_t widx = ((size_t)(ky*3+kx)*COUT + ci)*32 + lane;
                    ulonglong2 wA = ((const ulonglong2*)g_rw01)[widx];  // g0,g1
                    ulonglong2 wB = ((const ulonglong2*)g_rw23)[widx];  // g2,g3
                    #pragma unroll
                    for (int p = 0; p < 4; p++) {
                        const u64 s2 = hv2[p + kx];
                        fma_x2(acc[0][p], s2, wA.x);
                        fma_x2(acc[1][p], s2, wA.y);
                        fma_x2(acc[2][p], s2, wB.x);
                        fma_x2(acc[3][p], s2, wB.y);
                    }
                }
            }
        }
    }

    // BN constants for this thread's 2 channels
    float2 gm  = *(const float2*)(gamma + co0);
    float2 bt2 = *(const float2*)(beta  + co0);
    float2 mm  = *(const float2*)(mmean + co0);
    float2 mv  = *(const float2*)(mvar  + co0);
    float2 inv, add;
    inv.x = gm.x * rsqrtf(mv.x + 1e-3f); add.x = bt2.x - mm.x*inv.x;
    inv.y = gm.y * rsqrtf(mv.y + 1e-3f); add.y = bt2.y - mm.y*inv.y;

    const size_t pixrow = ((size_t)b*HH + py)*WW;
    #pragma unroll
    for (int p = 0; p < 4; p++) {
        const size_t pix = pixrow + px0 + p;

        float2 gi = unpack2(acc[0][p]);
        float2 gf = unpack2(acc[1][p]);
        float2 gg = unpack2(acc[2][p]);
        float2 go = unpack2(acc[3][p]);

        float2 i2, f2, o2;
        i2.x = hsig(gi.x); i2.y = hsig(gi.y);
        f2.x = hsig(gf.x); f2.y = hsig(gf.y);
        o2.x = hsig(go.x); o2.y = hsig(go.y);

        float* __restrict__ cp = g_c + pix*COUT + co0;
        float2 cold = FIRST ? make_float2(0.f,0.f) : *(const float2*)cp;

        float2 cn;
        cn.x = f2.x*cold.x + i2.x*tanhf(gg.x);
        cn.y = f2.y*cold.y + i2.y*tanhf(gg.y);
        *(float2*)cp = cn;

        float2 h2;
        h2.x = o2.x * tanhf(cn.x);
        h2.y = o2.y * tanhf(cn.y);
        *(float4*)(hnewd + pix*(COUT*2) + co0*2) = make_float4(h2.x, h2.x, h2.y, h2.y);

        float2 yv;
        yv.x = h2.x*inv.x + add.x;
        yv.y = h2.y*inv.y + add.y;
        float* __restrict__ yp = y + (gxrow + px0 + p)*COUT + co0;
        *(float2*)yp = yv;
    }
}

extern "C" void kernel_launch(void* const* d_in, const int* in_sizes, int n_in,
                              void* d_out, int out_size)
{
    const float* x      = (const float*)d_in[0];
    const float* wk     = (const float*)d_in[1];
    const float* rw     = (const float*)d_in[2];
    const float* bias   = (const float*)d_in[3];
    const float* gamma  = (const float*)d_in[4];
    const float* beta   = (const float*)d_in[5];
    const float* mmean  = (const float*)d_in[6];
    const float* mvar   = (const float*)d_in[7];
    float* y = (float*)d_out;

    // Prep: transpose/split weights (one-time per launch).
    const int n_prep = 9*COUT*32 + 9*CIN*32;
    prep_weights<<<(n_prep + 127)/128, 128>>>(wk, rw);

    // Phase 1: all input convs. 16384 blocks x 128 threads (16 px each).
    input_conv_kernel<<<BB*TT*HH*4, 128>>>(x, bias);

    // Phase 2: 16 sequential recurrent steps. 1024 blocks x 128 threads.
    const int nblk = BB*HH*4;
    step_kernel<true><<<nblk, 128>>>(y, 0, gamma, beta, mmean, mvar);
    for (int t = 1; t < TT; t++) {
        step_kernel<false><<<nblk, 128>>>(y, t, gamma, beta, mmean, mvar);
    }
}

// round 7
// speedup vs baseline: 1.5200x; 1.1519x over previous
#include <cuda_runtime.h>
#include <math.h>

#define BB 4
#define TT 16
#define HH 64
#define WW 64
#define CIN 32
#define COUT 64
#define GG (4*COUT)   // 256 gate channels

typedef unsigned long long u64;

// Scratch: gx for all (b,t) pixels: (B*T*H*W, 256) floats = 268MB
__device__ float g_gx[(size_t)BB*TT*HH*WW*GG];
// Duplicated ping-pong hidden state: each channel stored as {h,h} pair
__device__ float g_h0d[(size_t)BB*HH*WW*COUT*2];
__device__ float g_h1d[(size_t)BB*HH*WW*COUT*2];
// Cell state
__device__ float g_c [(size_t)BB*HH*WW*COUT];
// Split transposed weights: [k][ci][lane(32)][4 floats]
// g01: {g0c0,g0c1,g1c0,g1c1}   g23: {g2c0,g2c1,g3c0,g3c1}   (c0=2*lane)
__device__ float g_rw01[9*COUT*32*4];
__device__ float g_rw23[9*COUT*32*4];
__device__ float g_wk01[9*CIN*32*4];
__device__ float g_wk23[9*CIN*32*4];

__device__ __forceinline__ float hsig(float z) {
    return fminf(fmaxf(0.2f*z + 0.5f, 0.0f), 1.0f);
}

__device__ __forceinline__ void fma_x2(u64& acc, u64 s, u64 w) {
    asm("fma.rn.f32x2 %0, %1, %2, %3;" : "=l"(acc) : "l"(s), "l"(w), "l"(acc));
}
__device__ __forceinline__ u64 pack2(float s) {
    u64 r;
    asm("mov.b64 %0, {%1, %1};" : "=l"(r) : "f"(s));
    return r;
}
__device__ __forceinline__ float2 unpack2(u64 v) {
    float2 f;
    asm("mov.b64 {%0, %1}, %2;" : "=f"(f.x), "=f"(f.y) : "l"(v));
    return f;
}

// ---------------------------------------------------------------------------
// Weight transpose prep.
// ---------------------------------------------------------------------------
__global__ __launch_bounds__(128)
void prep_weights(const float* __restrict__ wk, const float* __restrict__ rw)
{
    const int i = blockIdx.x * 128 + threadIdx.x;
    if (i < 9*COUT*32) {
        const int j  = i & 31;
        const int ci = (i >> 5) & 63;
        const int k  = i >> 11;
        const float* s = rw + ((size_t)(k*COUT + ci))*GG + 2*j;
        ((float4*)g_rw01)[i] = make_float4(s[0],   s[1],   s[64],  s[65]);
        ((float4*)g_rw23)[i] = make_float4(s[128], s[129], s[192], s[193]);
    }
    const int m = i - 9*COUT*32;
    if (m >= 0 && m < 9*CIN*32) {
        const int j  = m & 31;
        const int ci = (m >> 5) & 31;
        const int k  = m >> 10;
        const float* s = wk + ((size_t)(k*CIN + ci))*GG + 2*j;
        ((float4*)g_wk01)[m] = make_float4(s[0],   s[1],   s[64],  s[65]);
        ((float4*)g_wk23)[m] = make_float4(s[128], s[129], s[192], s[193]);
    }
}

// ---------------------------------------------------------------------------
// Phase 1: input-to-gate conv.
// Thread: 8 pixels x (2 channels x 4 gates) = 32 packed accumulators.
// Block: 128 thr = 4 warps (8-px groups) x 32 lanes (channel pairs) = 32 px.
// Grid: B*T*H*2 = 8192.
// ---------------------------------------------------------------------------
__global__ __launch_bounds__(128, 4)
void input_conv_kernel(const float* __restrict__ x,
                       const float* __restrict__ bias)
{
    const int tx   = threadIdx.x;
    const int lane = tx & 31;
    const int co0  = lane * 2;
    const int pg   = tx >> 5;
    const int bid  = blockIdx.x;
    const int bt   = bid >> 7;
    const int r    = bid & 127;
    const int py   = r >> 1;
    const int px0  = (r & 1) * 32 + pg * 8;
    const bool okL = (px0 > 0);
    const bool okR = (px0 < WW - 8);

    u64 acc[4][8];
    #pragma unroll
    for (int g = 0; g < 4; g++) {
        u64 bv = *(const u64*)(bias + g*COUT + co0);
        #pragma unroll
        for (int p = 0; p < 8; p++) acc[g][p] = bv;
    }

    #pragma unroll
    for (int ky = 0; ky < 3; ky++) {
        const int iy = py + ky - 1;
        if ((unsigned)iy >= HH) continue;
        const float* __restrict__ xrow = x + ((size_t)(bt*HH + iy)*WW)*CIN;
        #pragma unroll 1
        for (int ci = 0; ci < CIN; ci++) {
            u64 hv2[10];
            hv2[0] = okL ? pack2(xrow[(size_t)(px0-1)*CIN + ci]) : 0ULL;
            #pragma unroll
            for (int j = 1; j < 9; j++)
                hv2[j] = pack2(xrow[(size_t)(px0-1+j)*CIN + ci]);
            hv2[9] = okR ? pack2(xrow[(size_t)(px0+8)*CIN + ci]) : 0ULL;
            #pragma unroll
            for (int kx = 0; kx < 3; kx++) {
                const size_t widx = ((size_t)(ky*3+kx)*CIN + ci)*32 + lane;
                ulonglong2 wA = ((const ulonglong2*)g_wk01)[widx];  // g0,g1
                ulonglong2 wB = ((const ulonglong2*)g_wk23)[widx];  // g2,g3
                #pragma unroll
                for (int p = 0; p < 8; p++) {
                    const u64 s2 = hv2[p + kx];
                    fma_x2(acc[0][p], s2, wA.x);
                    fma_x2(acc[1][p], s2, wA.y);
                    fma_x2(acc[2][p], s2, wB.x);
                    fma_x2(acc[3][p], s2, wB.y);
                }
            }
        }
    }

    const size_t rowbase = ((size_t)bt*HH + py)*WW;
    #pragma unroll
    for (int p = 0; p < 8; p++) {
        float* __restrict__ o = g_gx + (rowbase + px0 + p)*GG + co0;
        *(u64*)(o + 0*COUT) = acc[0][p];
        *(u64*)(o + 1*COUT) = acc[1][p];
        *(u64*)(o + 2*COUT) = acc[2][p];
        *(u64*)(o + 3*COUT) = acc[3][p];
    }
}

// ---------------------------------------------------------------------------
// Phase 2: one recurrent step. h stored duplicated ({h,h} per channel) so
// halo reads are direct LDG.64 of the packed broadcast operand.
// Thread: 8 pixels x (2 channels x 4 gates) = 32 packed accumulators.
// Block: 128 thr = 4 warps x 32 lanes = 32 px. Grid: B*H*2 = 512.
// ---------------------------------------------------------------------------
template<bool FIRST>
__global__ __launch_bounds__(128, 4)
void step_kernel(float* __restrict__ y,
                 const int t,
                 const float* __restrict__ gamma,
                 const float* __restrict__ beta,
                 const float* __restrict__ mmean,
                 const float* __restrict__ mvar)
{
    const float* __restrict__ hprevd = (t & 1) ? g_h0d : g_h1d;
    float*       __restrict__ hnewd  = (t & 1) ? g_h1d : g_h0d;

    const int tx   = threadIdx.x;
    const int lane = tx & 31;
    const int co0  = lane * 2;
    const int pg   = tx >> 5;
    const int bid  = blockIdx.x;
    const int b    = bid >> 7;
    const int r    = bid & 127;
    const int py   = r >> 1;
    const int px0  = (r & 1) * 32 + pg * 8;
    const bool okL = (px0 > 0);
    const bool okR = (px0 < WW - 8);

    u64 acc[4][8];
    const size_t gxrow = ((size_t)(b*TT + t)*HH + py)*WW;
    #pragma unroll
    for (int p = 0; p < 8; p++) {
        const float* __restrict__ gp = g_gx + (gxrow + px0 + p)*GG + co0;
        acc[0][p] = *(const u64*)(gp + 0*COUT);
        acc[1][p] = *(const u64*)(gp + 1*COUT);
        acc[2][p] = *(const u64*)(gp + 2*COUT);
        acc[3][p] = *(const u64*)(gp + 3*COUT);
    }

    if (!FIRST) {
        #pragma unroll
        for (int ky = 0; ky < 3; ky++) {
            const int iy = py + ky - 1;
            if ((unsigned)iy >= HH) continue;
            const float* __restrict__ hrow = hprevd + ((size_t)(b*HH + iy)*WW)*(COUT*2);
            #pragma unroll 1
            for (int ci = 0; ci < COUT; ci++) {
                u64 hv2[10];
                hv2[0] = okL ? *(const u64*)(hrow + (size_t)(px0-1)*(COUT*2) + ci*2) : 0ULL;
                #pragma unroll
                for (int j = 1; j < 9; j++)
                    hv2[j] = *(const u64*)(hrow + (size_t)(px0-1+j)*(COUT*2) + ci*2);
                hv2[9] = okR ? *(const u64*)(hrow + (size_t)(px0+8)*(COUT*2) + ci*2) : 0ULL;
                #pragma unroll
                for (int kx = 0; kx < 3; kx++) {
                    const size_t widx = ((size_t)(ky*3+kx)*COUT + ci)*32 + lane;
                    ulonglong2 wA = ((const ulonglong2*)g_rw01)[widx];  // g0,g1
                    ulonglong2 wB = ((const ulonglong2*)g_rw23)[widx];  // g2,g3
                    #pragma unroll
                    for (int p = 0; p < 8; p++) {
                        const u64 s2 = hv2[p + kx];
                        fma_x2(acc[0][p], s2, wA.x);
                        fma_x2(acc[1][p], s2, wA.y);
                        fma_x2(acc[2][p], s2, wB.x);
                        fma_x2(acc[3][p], s2, wB.y);
                    }
                }
            }
        }
    }

    // BN constants for this thread's 2 channels
    float2 gm  = *(const float2*)(gamma + co0);
    float2 bt2 = *(const float2*)(beta  + co0);
    float2 mm  = *(const float2*)(mmean + co0);
    float2 mv  = *(const float2*)(mvar  + co0);
    float2 inv, add;
    inv.x = gm.x * rsqrtf(mv.x + 1e-3f); add.x = bt2.x - mm.x*inv.x;
    inv.y = gm.y * rsqrtf(mv.y + 1e-3f); add.y = bt2.y - mm.y*inv.y;

    const size_t pixrow = ((size_t)b*HH + py)*WW;
    #pragma unroll
    for (int p = 0; p < 8; p++) {
        const size_t pix = pixrow + px0 + p;

        float2 gi = unpack2(acc[0][p]);
        float2 gf = unpack2(acc[1][p]);
        float2 gg = unpack2(acc[2][p]);
        float2 go = unpack2(acc[3][p]);

        float2 i2, f2, o2;
        i2.x = hsig(gi.x); i2.y = hsig(gi.y);
        f2.x = hsig(gf.x); f2.y = hsig(gf.y);
        o2.x = hsig(go.x); o2.y = hsig(go.y);

        float* __restrict__ cp = g_c + pix*COUT + co0;
        float2 cold = FIRST ? make_float2(0.f,0.f) : *(const float2*)cp;

        float2 cn;
        cn.x = f2.x*cold.x + i2.x*tanhf(gg.x);
        cn.y = f2.y*cold.y + i2.y*tanhf(gg.y);
        *(float2*)cp = cn;

        float2 h2;
        h2.x = o2.x * tanhf(cn.x);
        h2.y = o2.y * tanhf(cn.y);
        *(float4*)(hnewd + pix*(COUT*2) + co0*2) = make_float4(h2.x, h2.x, h2.y, h2.y);

        float2 yv;
        yv.x = h2.x*inv.x + add.x;
        yv.y = h2.y*inv.y + add.y;
        float* __restrict__ yp = y + (gxrow + px0 + p)*COUT + co0;
        *(float2*)yp = yv;
    }
}

extern "C" void kernel_launch(void* const* d_in, const int* in_sizes, int n_in,
                              void* d_out, int out_size)
{
    const float* x      = (const float*)d_in[0];
    const float* wk     = (const float*)d_in[1];
    const float* rw     = (const float*)d_in[2];
    const float* bias   = (const float*)d_in[3];
    const float* gamma  = (const float*)d_in[4];
    const float* beta   = (const float*)d_in[5];
    const float* mmean  = (const float*)d_in[6];
    const float* mvar   = (const float*)d_in[7];
    float* y = (float*)d_out;

    // Prep: transpose/split weights (one-time per launch).
    const int n_prep = 9*COUT*32 + 9*CIN*32;
    prep_weights<<<(n_prep + 127)/128, 128>>>(wk, rw);

    // Phase 1: all input convs. 8192 blocks x 128 threads (32 px each).
    input_conv_kernel<<<BB*TT*HH*2, 128>>>(x, bias);

    // Phase 2: 16 sequential recurrent steps. 512 blocks x 128 threads.
    const int nblk = BB*HH*2;
    step_kernel<true><<<nblk, 128>>>(y, 0, gamma, beta, mmean, mvar);
    for (int t = 1; t < TT; t++) {
        step_kernel<false><<<nblk, 128>>>(y, t, gamma, beta, mmean, mvar);
    }
}